// round 9
// baseline (speedup 1.0000x reference)
#include <cuda_runtime.h>
#include <math.h>

// Problem constants
#define PB 16      // batch
#define PS 4096    // sequence
#define PD 64      // head dim
#define PH 8       // n_hashes
#define PNB 64     // n_buckets
#define PCHUNKS 512 // chunks per batch (PH * PNB), each of 64 tokens

typedef unsigned long long u64;

// ---- packed fp32x2 helpers (Blackwell FFMA2 path) -------------------------
__device__ __forceinline__ u64 pack2(float x, float y) {
    u64 r; asm("mov.b64 %0, {%1, %2};" : "=l"(r) : "f"(x), "f"(y)); return r;
}
__device__ __forceinline__ float2 unpack2(u64 p) {
    float2 v; asm("mov.b64 {%0, %1}, %2;" : "=f"(v.x), "=f"(v.y) : "l"(p)); return v;
}
__device__ __forceinline__ u64 ffma2(u64 a, u64 b, u64 c) {
    asm("fma.rn.f32x2 %0, %1, %2, %0;" : "+l"(c) : "l"(a), "l"(b));
    return c;
}

// ---------------- scratch (device globals; no allocation allowed) ----------
__device__ unsigned char g_bucket[PB * PH * PS];            // 512 KB
__device__ int           g_st[PB * PH * PS];                // 2 MB   sorted pos -> original t
__device__ float         g_lse[PB * PH * PS];               // 2 MB   [b][h][t]
__device__ float         g_o[(size_t)PB * PH * PS * PD];    // 128 MB [b][h][t][d]

// ---------------------------------------------------------------------------
// Kernel 1: hashing. rotated[i] = sum_f qk[b,t,f] * rot[f,h,i]; argmax over
// [rotated, -rotated] with first-occurrence tie-breaking (match jnp.argmax).
// ---------------------------------------------------------------------------
__global__ void __launch_bounds__(256) k_hash(
    const float* __restrict__ qk, const float* __restrict__ rot,
    float* __restrict__ out_tail, int write_buckets)
{
    __shared__ float rot_s[64 * 32];   // rotations for one hash round: [f][i]
    int b = blockIdx.x >> 4;
    int t = ((blockIdx.x & 15) << 8) + threadIdx.x;

    const float* qr = qk + ((size_t)b * PS + t) * PD;
    float q[64];
#pragma unroll
    for (int f4 = 0; f4 < 16; f4++) {
        float4 v4 = ((const float4*)qr)[f4];
        q[f4 * 4 + 0] = v4.x; q[f4 * 4 + 1] = v4.y;
        q[f4 * 4 + 2] = v4.z; q[f4 * 4 + 3] = v4.w;
    }

    for (int h = 0; h < PH; h++) {
        __syncthreads();
        for (int e = threadIdx.x; e < 2048; e += 256) {
            int f = e >> 5, i = e & 31;
            rot_s[e] = rot[f * 256 + h * 32 + i];  // rot layout [f][h][i] (b bcast)
        }
        __syncthreads();

        u64 acc[16];
#pragma unroll
        for (int p = 0; p < 16; p++) acc[p] = 0ull;   // (0.0f, 0.0f)

        for (int f = 0; f < 64; f++) {
            u64 qb = pack2(q[f], q[f]);
            const ulonglong2* rr = (const ulonglong2*)&rot_s[f * 32]; // LDS.128 bcast
#pragma unroll
            for (int p2 = 0; p2 < 8; p2++) {
                ulonglong2 vv = rr[p2];
                acc[2 * p2 + 0] = ffma2(qb, vv.x, acc[2 * p2 + 0]);
                acc[2 * p2 + 1] = ffma2(qb, vv.y, acc[2 * p2 + 1]);
            }
        }

        float bestp = -1e30f, bestn = -1e30f;
        int ip = 0, inn = 0;
#pragma unroll
        for (int p = 0; p < 16; p++) {
            float2 a = unpack2(acc[p]);
            int i0 = 2 * p, i1 = 2 * p + 1;
            if ( a.x > bestp) { bestp =  a.x; ip  = i0; }
            if (-a.x > bestn) { bestn = -a.x; inn = i0; }
            if ( a.y > bestp) { bestp =  a.y; ip  = i1; }
            if (-a.y > bestn) { bestn = -a.y; inn = i1; }
        }
        int idx = (bestp >= bestn) ? ip : (32 + inn);  // plus-half wins ties
        g_bucket[((size_t)b * PH + h) * PS + t] = (unsigned char)idx;
        if (write_buckets)
            out_tail[((size_t)b * PH + h) * PS + t] = (float)(idx + h * PNB);
    }
}

// ---------------------------------------------------------------------------
// Kernel 2: stable counting sort per (b,h): 4096 tokens into 64 buckets by
// (bucket, t) — exactly jnp.argsort of S*bucket + t. grid: PB*PH, 128 threads.
// ---------------------------------------------------------------------------
__global__ void __launch_bounds__(128) k_sort()
{
    __shared__ unsigned char sb[4096];
    __shared__ int hist[64];
    __shared__ int offs[64];
    int bh = blockIdx.x;
    int tid = threadIdx.x;

    if (tid < 64) hist[tid] = 0;
    const unsigned int* src = (const unsigned int*)(g_bucket + (size_t)bh * PS);
    unsigned int* dstb = (unsigned int*)sb;
    for (int i = tid; i < 1024; i += 128) dstb[i] = src[i];
    __syncthreads();

    for (int t = tid; t < 4096; t += 128) atomicAdd(&hist[sb[t]], 1);
    __syncthreads();

    if (tid == 0) {
        int run = 0;
        for (int k = 0; k < 64; k++) { offs[k] = run; run += hist[k]; }
    }
    __syncthreads();

    if (tid < 64) {
        int k = tid;
        int pos = offs[k];
        int* dst = g_st + (size_t)bh * PS;
        for (int t = 0; t < 4096; t++)
            if (sb[t] == (unsigned char)k) dst[pos++] = t;  // stable: t ascending
    }
}

// ---------------------------------------------------------------------------
// Kernel 3: chunk attention. FFMA2 with PRE-DUPLICATED broadcast operands:
//   Q stored as (q,q) u64 pairs, P written post-softmax as (p,p) pairs into
//   the SAME smem region (Q dead by then). One LDS.128 = two packed operands,
//   zero pack-MOVs in both matmul loops. K-normalization is two-pass (no
//   r[64] register blowup). __launch_bounds__(256,2) pins 2 CTAs/SM.
// Thread map: ty=tid>>4 (rows i = ty+16*ii), tx=tid&15 (j/d pairs 2tx+32g).
// ---------------------------------------------------------------------------
#define R_PAIRS   (64 * 132)          // p_dup: 64 rows x 132 pair-stride (u64)
#define SM_R      (R_PAIRS * 2)       // floats in the aliased Q-dup/P-dup region
#define SM_KV     (64 * 130)          // K^T stride 130; reused for V [128][64]
#define SMEM3_BYTES ((SM_R + SM_KV) * 4 + 128 * 4)

__global__ void __launch_bounds__(256, 2) k_attn(
    const float* __restrict__ qk, const float* __restrict__ v)
{
    extern __shared__ float sm[];
    u64*   dup  = (u64*)sm;               // Q-dup [i*64+kk], later P-dup [i*132+j]
    float* kv_s = sm + SM_R;              // K^T: [f*130 + j]; later V: [j*64 + d]
    int*   st_k = (int*)(kv_s + SM_KV);   // 128 orig positions (0..63 = Q chunk)

    int tid = threadIdx.x;
    int b = blockIdx.x >> 9;
    int c = blockIdx.x & 511;
    int h  = c >> 6;
    int cp = (c + 511) & 511;
    int hp = cp >> 6;

    if (tid < 64) {
        st_k[tid]      = g_st[((size_t)b * PH + h ) * PS + (c  & 63) * 64 + tid];
        st_k[64 + tid] = g_st[((size_t)b * PH + hp) * PS + (cp & 63) * 64 + tid];
    }
    __syncthreads();

    // ---- load Q, store duplicated pairs (q,q) ----
    {
        int i  = tid >> 2;
        int f0 = (tid & 3) * 16;
        const float* row = qk + ((size_t)b * PS + st_k[i]) * PD + f0;
#pragma unroll
        for (int u = 0; u < 4; u++) {
            float4 v4 = ((const float4*)row)[u];
            float4* d = (float4*)&dup[i * 64 + f0 + 4 * u];
            d[0] = make_float4(v4.x, v4.x, v4.y, v4.y);   // STS.128
            d[1] = make_float4(v4.z, v4.z, v4.w, v4.w);
        }
    }
    // ---- load K: two-pass row-normalization (no big register array) ----
    if (tid < 128) {
        int j = tid;
        const float* row = qk + ((size_t)b * PS + st_k[j]) * PD;
        float ss = 0.f;
#pragma unroll
        for (int u = 0; u < 16; u++) {
            float4 v4 = ((const float4*)row)[u];
            ss += v4.x * v4.x + v4.y * v4.y + v4.z * v4.z + v4.w * v4.w;
        }
        float inv = 1.0f / fmaxf(sqrtf(ss), 1e-12f);
#pragma unroll
        for (int u = 0; u < 16; u++) {
            float4 v4 = ((const float4*)row)[u];   // L1 hit (just loaded)
            int f = 4 * u;
            kv_s[(f + 0) * 130 + j] = v4.x * inv;
            kv_s[(f + 1) * 130 + j] = v4.y * inv;
            kv_s[(f + 2) * 130 + j] = v4.z * inv;
            kv_s[(f + 3) * 130 + j] = v4.w * inv;
        }
    }
    __syncthreads();

    int ty = tid >> 4, tx = tid & 15;
    float  row_inv[4];                 // deferred 1/s per owned row
    float2 p[4][4];                    // softmax result held in registers

    // ---- dots = Q K^T (FFMA2; Q pairs via LDS.128, K pairs via LDS.64) ----
    {
        u64 acc[4][4];
#pragma unroll
        for (int ii = 0; ii < 4; ii++)
#pragma unroll
            for (int g = 0; g < 4; g++) acc[ii][g] = 0ull;

        for (int kk0 = 0; kk0 < 64; kk0 += 2) {
            ulonglong2 qp[4];
#pragma unroll
            for (int ii = 0; ii < 4; ii++)
                qp[ii] = *(const ulonglong2*)&dup[(ty + ii * 16) * 64 + kk0]; // LDS.128
#pragma unroll
            for (int u = 0; u < 2; u++) {
                int kk = kk0 + u;
                u64 kp[4];
#pragma unroll
                for (int g = 0; g < 4; g++)
                    kp[g] = *(const u64*)&kv_s[kk * 130 + 2 * tx + 32 * g]; // LDS.64
#pragma unroll
                for (int ii = 0; ii < 4; ii++) {
                    u64 qb = u ? qp[ii].y : qp[ii].x;
#pragma unroll
                    for (int g = 0; g < 4; g++)
                        acc[ii][g] = ffma2(qb, kp[g], acc[ii][g]);
                }
            }
        }

        // ---- scale + self-mask + register softmax (16-lane shfl rows) ----
        int tj[8];
#pragma unroll
        for (int g = 0; g < 4; g++) {
            tj[2 * g]     = st_k[2 * tx + 32 * g];
            tj[2 * g + 1] = st_k[2 * tx + 32 * g + 1];
        }
#pragma unroll
        for (int ii = 0; ii < 4; ii++) {
            int i = ty + ii * 16;
            int ti = st_k[i];
#pragma unroll
            for (int g = 0; g < 4; g++) {
                p[ii][g] = unpack2(acc[ii][g]);
                p[ii][g].x *= 0.125f; p[ii][g].y *= 0.125f;
                if (ti == tj[2 * g])     p[ii][g].x = -1e5f;
                if (ti == tj[2 * g + 1]) p[ii][g].y = -1e5f;
            }
            float m = fmaxf(fmaxf(fmaxf(p[ii][0].x, p[ii][0].y), fmaxf(p[ii][1].x, p[ii][1].y)),
                            fmaxf(fmaxf(p[ii][2].x, p[ii][2].y), fmaxf(p[ii][3].x, p[ii][3].y)));
            m = fmaxf(m, __shfl_xor_sync(0xffffffffu, m, 1));
            m = fmaxf(m, __shfl_xor_sync(0xffffffffu, m, 2));
            m = fmaxf(m, __shfl_xor_sync(0xffffffffu, m, 4));
            m = fmaxf(m, __shfl_xor_sync(0xffffffffu, m, 8));
            float s = 0.f;
#pragma unroll
            for (int g = 0; g < 4; g++) {
                p[ii][g].x = __expf(p[ii][g].x - m);
                p[ii][g].y = __expf(p[ii][g].y - m);
                s += p[ii][g].x + p[ii][g].y;
            }
            s += __shfl_xor_sync(0xffffffffu, s, 1);
            s += __shfl_xor_sync(0xffffffffu, s, 2);
            s += __shfl_xor_sync(0xffffffffu, s, 4);
            s += __shfl_xor_sync(0xffffffffu, s, 8);
            row_inv[ii] = 1.0f / s;
            if (tx == 0)
                g_lse[((size_t)b * PH + h) * PS + ti] = m + __logf(s);
        }
    }
    __syncthreads();   // all Q-dup + K^T reads done -> safe to overwrite both

    // ---- write P duplicated pairs; load V into kv_s ----
    {
#pragma unroll
        for (int ii = 0; ii < 4; ii++) {
            int i = ty + ii * 16;
#pragma unroll
            for (int g = 0; g < 4; g++) {
                float4* d = (float4*)&dup[i * 132 + 2 * tx + 32 * g];
                *d = make_float4(p[ii][g].x, p[ii][g].x, p[ii][g].y, p[ii][g].y);
            }
        }
        int j  = tid >> 1;
        int d0 = (tid & 1) * 32;
        const float* row = v + ((size_t)b * PS + st_k[j]) * PD + d0;
        float* dv = kv_s + j * 64 + d0;
#pragma unroll
        for (int u = 0; u < 8; u++)
            ((float4*)dv)[u] = ((const float4*)row)[u];
    }
    __syncthreads();

    // ---- O = P V (FFMA2; P pairs via LDS.128, V pairs via LDS.64) ----
    {
        u64 oacc[4][2];
#pragma unroll
        for (int ii = 0; ii < 4; ii++) { oacc[ii][0] = 0ull; oacc[ii][1] = 0ull; }

        for (int j0 = 0; j0 < 128; j0 += 2) {
            ulonglong2 pp[4];
#pragma unroll
            for (int ii = 0; ii < 4; ii++)
                pp[ii] = *(const ulonglong2*)&dup[(ty + ii * 16) * 132 + j0]; // LDS.128
#pragma unroll
            for (int u = 0; u < 2; u++) {
                int j = j0 + u;
                u64 vp0 = *(const u64*)&kv_s[j * 64 + 2 * tx];       // LDS.64
                u64 vp1 = *(const u64*)&kv_s[j * 64 + 2 * tx + 32];
#pragma unroll
                for (int ii = 0; ii < 4; ii++) {
                    u64 pb = u ? pp[ii].y : pp[ii].x;
                    oacc[ii][0] = ffma2(pb, vp0, oacc[ii][0]);
                    oacc[ii][1] = ffma2(pb, vp1, oacc[ii][1]);
                }
            }
        }
#pragma unroll
        for (int ii = 0; ii < 4; ii++) {
            int i = ty + ii * 16;
            float inv = row_inv[ii];
            size_t base = (((size_t)b * PH + h) * PS + st_k[i]) * (size_t)PD;
#pragma unroll
            for (int g = 0; g < 2; g++) {
                float2 a = unpack2(oacc[ii][g]);
                a.x *= inv; a.y *= inv;
                *(float2*)&g_o[base + 2 * tx + 32 * g] = a;  // STG.64, coalesced
            }
        }
    }
}

// ---------------------------------------------------------------------------
// no-op launch to shift the fixed ncu capture index (profiling aid, ~0 cost)
// ---------------------------------------------------------------------------
__global__ void k_nop() {}

// ---------------------------------------------------------------------------
// Kernel 4: combine hash rounds: w_h = exp(lse_h - logsumexp_h), out = sum w_h o_h.
// ---------------------------------------------------------------------------
__global__ void __launch_bounds__(256) k_combine(float* __restrict__ out)
{
    __shared__ float sw[32 * 8];
    int b  = blockIdx.x >> 7;
    int t0 = (blockIdx.x & 127) * 32;
    int tid = threadIdx.x;
    int tl = tid >> 3, h = tid & 7;
    int t = t0 + tl;

    float l = g_lse[((size_t)b * PH + h) * PS + t];
    float m = l;
#pragma unroll
    for (int o = 4; o; o >>= 1) m = fmaxf(m, __shfl_xor_sync(0xffffffffu, m, o));
    float s = __expf(l - m);
#pragma unroll
    for (int o = 4; o; o >>= 1) s += __shfl_xor_sync(0xffffffffu, s, o);
    sw[tl * 8 + h] = __expf(l - (m + __logf(s)));
    __syncthreads();

#pragma unroll
    for (int r = 0; r < 8; r++) {
        int idx = tid + r * 256;
        int tl2 = idx >> 6, d = idx & 63;
        int t2 = t0 + tl2;
        float acc = 0.f;
#pragma unroll
        for (int hh = 0; hh < 8; hh++)
            acc += g_o[(((size_t)b * PH + hh) * PS + t2) * (size_t)PD + d] * sw[tl2 * 8 + hh];
        out[((size_t)b * PS + t2) * (size_t)PD + d] = acc;
    }
}

// ---------------------------------------------------------------------------
extern "C" void kernel_launch(void* const* d_in, const int* in_sizes, int n_in,
                              void* d_out, int out_size)
{
    (void)n_in; (void)in_sizes;
    const float* qk  = (const float*)d_in[0];
    const float* v   = (const float*)d_in[1];
    const float* rot = (const float*)d_in[2];
    float* out = (float*)d_out;

    const int n_main = PB * PS * PD;            // 4194304
    const int n_buck = PB * PH * PS;            // 524288
    int write_buckets = (out_size >= n_main + n_buck) ? 1 : 0;

    cudaFuncSetAttribute(k_attn, cudaFuncAttributeMaxDynamicSharedMemorySize,
                         SMEM3_BYTES);

    k_hash<<<PB * (PS / 256), 256>>>(qk, rot, out + n_main, write_buckets);
    k_sort<<<PB * PH, 128>>>();
    k_attn<<<PB * PCHUNKS, 256, SMEM3_BYTES>>>(qk, v);
    k_nop<<<1, 32>>>();
    k_combine<<<PB * (PS / 32), 256>>>(out);
}

// round 10
// speedup vs baseline: 1.1987x; 1.1987x over previous
#include <cuda_runtime.h>
#include <cuda_fp16.h>
#include <math.h>

// Problem constants
#define PB 16      // batch
#define PS 4096    // sequence
#define PD 64      // head dim
#define PH 8       // n_hashes
#define PNB 64     // n_buckets
#define PCHUNKS 512 // chunks per batch (PH * PNB), each of 64 tokens

typedef unsigned long long u64;

// ---- packed fp32x2 helpers (Blackwell FFMA2 path) -------------------------
__device__ __forceinline__ u64 pack2(float x, float y) {
    u64 r; asm("mov.b64 %0, {%1, %2};" : "=l"(r) : "f"(x), "f"(y)); return r;
}
__device__ __forceinline__ float2 unpack2(u64 p) {
    float2 v; asm("mov.b64 {%0, %1}, %2;" : "=f"(v.x), "=f"(v.y) : "l"(p)); return v;
}
__device__ __forceinline__ u64 ffma2(u64 a, u64 b, u64 c) {
    asm("fma.rn.f32x2 %0, %1, %2, %0;" : "+l"(c) : "l"(a), "l"(b));
    return c;
}

// ---------------- scratch (device globals; no allocation allowed) ----------
__device__ unsigned char g_bucket[PB * PH * PS];            // 512 KB
__device__ int           g_st[PB * PH * PS];                // 2 MB   sorted pos -> original t
__device__ float         g_lse[PB * PH * PS];               // 2 MB   [b][h][t]
__device__ __half        g_o[(size_t)PB * PH * PS * PD];    // 64 MB  [b][h][t][d] fp16

// ---------------------------------------------------------------------------
// Kernel 1: hashing. rotated[i] = sum_f qk[b,t,f] * rot[f,h,i]; argmax over
// [rotated, -rotated] with first-occurrence tie-breaking (match jnp.argmax).
// ---------------------------------------------------------------------------
__global__ void __launch_bounds__(256) k_hash(
    const float* __restrict__ qk, const float* __restrict__ rot,
    float* __restrict__ out_tail, int write_buckets)
{
    __shared__ float rot_s[64 * 32];   // rotations for one hash round: [f][i]
    int b = blockIdx.x >> 4;
    int t = ((blockIdx.x & 15) << 8) + threadIdx.x;

    const float* qr = qk + ((size_t)b * PS + t) * PD;
    float q[64];
#pragma unroll
    for (int f4 = 0; f4 < 16; f4++) {
        float4 v4 = ((const float4*)qr)[f4];
        q[f4 * 4 + 0] = v4.x; q[f4 * 4 + 1] = v4.y;
        q[f4 * 4 + 2] = v4.z; q[f4 * 4 + 3] = v4.w;
    }

    for (int h = 0; h < PH; h++) {
        __syncthreads();
        for (int e = threadIdx.x; e < 2048; e += 256) {
            int f = e >> 5, i = e & 31;
            rot_s[e] = rot[f * 256 + h * 32 + i];  // rot layout [f][h][i] (b bcast)
        }
        __syncthreads();

        u64 acc[16];
#pragma unroll
        for (int p = 0; p < 16; p++) acc[p] = 0ull;   // (0.0f, 0.0f)

        for (int f = 0; f < 64; f++) {
            u64 qb = pack2(q[f], q[f]);
            const ulonglong2* rr = (const ulonglong2*)&rot_s[f * 32]; // LDS.128 bcast
#pragma unroll
            for (int p2 = 0; p2 < 8; p2++) {
                ulonglong2 vv = rr[p2];
                acc[2 * p2 + 0] = ffma2(qb, vv.x, acc[2 * p2 + 0]);
                acc[2 * p2 + 1] = ffma2(qb, vv.y, acc[2 * p2 + 1]);
            }
        }

        float bestp = -1e30f, bestn = -1e30f;
        int ip = 0, inn = 0;
#pragma unroll
        for (int p = 0; p < 16; p++) {
            float2 a = unpack2(acc[p]);
            int i0 = 2 * p, i1 = 2 * p + 1;
            if ( a.x > bestp) { bestp =  a.x; ip  = i0; }
            if (-a.x > bestn) { bestn = -a.x; inn = i0; }
            if ( a.y > bestp) { bestp =  a.y; ip  = i1; }
            if (-a.y > bestn) { bestn = -a.y; inn = i1; }
        }
        int idx = (bestp >= bestn) ? ip : (32 + inn);  // plus-half wins ties
        g_bucket[((size_t)b * PH + h) * PS + t] = (unsigned char)idx;
        if (write_buckets)
            out_tail[((size_t)b * PH + h) * PS + t] = (float)(idx + h * PNB);
    }
}

// ---------------------------------------------------------------------------
// Kernel 2: stable counting sort per (b,h): 4096 tokens into 64 buckets by
// (bucket, t) — exactly jnp.argsort of S*bucket + t. grid: PB*PH, 128 threads.
// ---------------------------------------------------------------------------
__global__ void __launch_bounds__(128) k_sort()
{
    __shared__ unsigned char sb[4096];
    __shared__ int hist[64];
    __shared__ int offs[64];
    int bh = blockIdx.x;
    int tid = threadIdx.x;

    if (tid < 64) hist[tid] = 0;
    const unsigned int* src = (const unsigned int*)(g_bucket + (size_t)bh * PS);
    unsigned int* dstb = (unsigned int*)sb;
    for (int i = tid; i < 1024; i += 128) dstb[i] = src[i];
    __syncthreads();

    for (int t = tid; t < 4096; t += 128) atomicAdd(&hist[sb[t]], 1);
    __syncthreads();

    if (tid == 0) {
        int run = 0;
        for (int k = 0; k < 64; k++) { offs[k] = run; run += hist[k]; }
    }
    __syncthreads();

    if (tid < 64) {
        int k = tid;
        int pos = offs[k];
        int* dst = g_st + (size_t)bh * PS;
        for (int t = 0; t < 4096; t++)
            if (sb[t] == (unsigned char)k) dst[pos++] = t;  // stable: t ascending
    }
}

// ---------------------------------------------------------------------------
// Kernel 3: chunk attention (R6 proven structure). FFMA2 + register softmax.
//   Q (64x64, q_s stride 68, LDS.128 over kk), K^T (stride 130), softmax in
//   registers with 16-lane shfl rows, P written once (stride 132, LDS.128
//   over j), O = P V with deferred 1/s, fp16 scatter by st (fused unsort).
// Thread map: ty=tid>>4 (rows i = ty+16*ii), tx=tid&15 (j/d pairs 2tx+32g).
// 256 threads, dynamic smem 84992 B.
// ---------------------------------------------------------------------------
#define SM_Q   (64 * 68)     // 4352 floats  (row stride 68 -> 272B, 16B-aligned)
#define SM_KV  (64 * 130)    // 8320 floats  (K^T pad 130; reused for V [128][64])
#define SM_DOT (64 * 132)    // 8448 floats  (P stride 132 -> 528B, 16B-aligned)
#define SMEM3_BYTES ((SM_Q + SM_KV + SM_DOT) * 4 + 128 * 4)

__global__ void __launch_bounds__(256) k_attn(
    const float* __restrict__ qk, const float* __restrict__ v)
{
    extern __shared__ float sm[];
    float* q_s  = sm;                     // [i*68 + f]
    float* kv_s = sm + SM_Q;              // K^T: [f*130 + j]; later V: [j*64 + d]
    float* p_s  = sm + SM_Q + SM_KV;      // P: [i*132 + j] (post-softmax only)
    int*   st_k = (int*)(p_s + SM_DOT);   // 128 orig positions (0..63 = Q chunk)

    int tid = threadIdx.x;
    int b = blockIdx.x >> 9;
    int c = blockIdx.x & 511;
    int h  = c >> 6;
    int cp = (c + 511) & 511;
    int hp = cp >> 6;

    if (tid < 64) {
        st_k[tid]      = g_st[((size_t)b * PH + h ) * PS + (c  & 63) * 64 + tid];
        st_k[64 + tid] = g_st[((size_t)b * PH + hp) * PS + (cp & 63) * 64 + tid];
    }
    __syncthreads();

    // ---- load Q (raw) ----
    {
        int i  = tid >> 2;
        int f0 = (tid & 3) * 16;
        const float* row = qk + ((size_t)b * PS + st_k[i]) * PD + f0;
#pragma unroll
        for (int u = 0; u < 4; u++) {
            float4 v4 = ((const float4*)row)[u];
            int f = f0 + u * 4;
            q_s[i * 68 + f + 0] = v4.x; q_s[i * 68 + f + 1] = v4.y;
            q_s[i * 68 + f + 2] = v4.z; q_s[i * 68 + f + 3] = v4.w;
        }
    }
    // ---- load K: row-normalized (clip 1e-12), transposed, stride 130 ----
    if (tid < 128) {
        int j = tid;
        const float* row = qk + ((size_t)b * PS + st_k[j]) * PD;
        float r[64];
        float ss = 0.f;
#pragma unroll
        for (int u = 0; u < 16; u++) {
            float4 v4 = ((const float4*)row)[u];
            r[u * 4 + 0] = v4.x; r[u * 4 + 1] = v4.y;
            r[u * 4 + 2] = v4.z; r[u * 4 + 3] = v4.w;
            ss += v4.x * v4.x + v4.y * v4.y + v4.z * v4.z + v4.w * v4.w;
        }
        float nrm = fmaxf(sqrtf(ss), 1e-12f);
        float inv = 1.0f / nrm;
#pragma unroll
        for (int f = 0; f < 64; f++) kv_s[f * 130 + j] = r[f] * inv;
    }
    __syncthreads();

    int ty = tid >> 4, tx = tid & 15;
    float row_inv[4];   // deferred 1/s per owned row (survives to PV epilogue)

    // ---- dots = Q K^T (FFMA2, kk-unrolled x4, LDS.128 Q) ----
    {
        u64 acc[4][4];
#pragma unroll
        for (int ii = 0; ii < 4; ii++)
#pragma unroll
            for (int g = 0; g < 4; g++) acc[ii][g] = 0ull;

        for (int kk0 = 0; kk0 < 64; kk0 += 4) {
            float qa[4][4];
#pragma unroll
            for (int ii = 0; ii < 4; ii++) {
                float4 q4 = *(const float4*)&q_s[(ty + ii * 16) * 68 + kk0]; // LDS.128
                qa[ii][0] = q4.x; qa[ii][1] = q4.y; qa[ii][2] = q4.z; qa[ii][3] = q4.w;
            }
#pragma unroll
            for (int u = 0; u < 4; u++) {
                int kk = kk0 + u;
                u64 kp[4];
#pragma unroll
                for (int g = 0; g < 4; g++)
                    kp[g] = *(const u64*)&kv_s[kk * 130 + 2 * tx + 32 * g]; // LDS.64
#pragma unroll
                for (int ii = 0; ii < 4; ii++) {
                    u64 qb = pack2(qa[ii][u], qa[ii][u]);
#pragma unroll
                    for (int g = 0; g < 4; g++)
                        acc[ii][g] = ffma2(qb, kp[g], acc[ii][g]);
                }
            }
        }

        // ---- scale + self-mask + register softmax (16-lane shfl rows) ----
        int tj[8];
#pragma unroll
        for (int g = 0; g < 4; g++) {
            tj[2 * g]     = st_k[2 * tx + 32 * g];
            tj[2 * g + 1] = st_k[2 * tx + 32 * g + 1];
        }
#pragma unroll
        for (int ii = 0; ii < 4; ii++) {
            int i = ty + ii * 16;
            int ti = st_k[i];
            float2 p[4];
#pragma unroll
            for (int g = 0; g < 4; g++) {
                p[g] = unpack2(acc[ii][g]);
                p[g].x *= 0.125f; p[g].y *= 0.125f;
                if (ti == tj[2 * g])     p[g].x = -1e5f;
                if (ti == tj[2 * g + 1]) p[g].y = -1e5f;
            }
            // row max across this thread's 8 + 16 lanes
            float m = fmaxf(fmaxf(fmaxf(p[0].x, p[0].y), fmaxf(p[1].x, p[1].y)),
                            fmaxf(fmaxf(p[2].x, p[2].y), fmaxf(p[3].x, p[3].y)));
            m = fmaxf(m, __shfl_xor_sync(0xffffffffu, m, 1));
            m = fmaxf(m, __shfl_xor_sync(0xffffffffu, m, 2));
            m = fmaxf(m, __shfl_xor_sync(0xffffffffu, m, 4));
            m = fmaxf(m, __shfl_xor_sync(0xffffffffu, m, 8));
            float s = 0.f;
#pragma unroll
            for (int g = 0; g < 4; g++) {
                p[g].x = __expf(p[g].x - m);
                p[g].y = __expf(p[g].y - m);
                s += p[g].x + p[g].y;
            }
            s += __shfl_xor_sync(0xffffffffu, s, 1);
            s += __shfl_xor_sync(0xffffffffu, s, 2);
            s += __shfl_xor_sync(0xffffffffu, s, 4);
            s += __shfl_xor_sync(0xffffffffu, s, 8);
            row_inv[ii] = 1.0f / s;     // normalization deferred to O epilogue
            // write unnormalized P once
#pragma unroll
            for (int g = 0; g < 4; g++)
                *(float2*)&p_s[i * 132 + 2 * tx + 32 * g] = p[g];
            if (tx == 0)
                g_lse[((size_t)b * PH + h) * PS + ti] = m + __logf(s);
        }
    }
    __syncthreads();   // all K^T reads done -> safe to overwrite kv_s with V

    // ---- load V into kv_s ----
    {
        int j  = tid >> 1;
        int d0 = (tid & 1) * 32;
        const float* row = v + ((size_t)b * PS + st_k[j]) * PD + d0;
        float* dv = kv_s + j * 64 + d0;
#pragma unroll
        for (int u = 0; u < 8; u++)
            ((float4*)dv)[u] = ((const float4*)row)[u];
    }
    __syncthreads();

    // ---- O = P V (FFMA2, j-unrolled x4, LDS.128 P), scale, fp16 scatter ----
    {
        u64 oacc[4][2];
#pragma unroll
        for (int ii = 0; ii < 4; ii++) { oacc[ii][0] = 0ull; oacc[ii][1] = 0ull; }

        for (int j0 = 0; j0 < 128; j0 += 4) {
            float pa[4][4];
#pragma unroll
            for (int ii = 0; ii < 4; ii++) {
                float4 p4 = *(const float4*)&p_s[(ty + ii * 16) * 132 + j0]; // LDS.128
                pa[ii][0] = p4.x; pa[ii][1] = p4.y; pa[ii][2] = p4.z; pa[ii][3] = p4.w;
            }
#pragma unroll
            for (int u = 0; u < 4; u++) {
                int j = j0 + u;
                u64 vp0 = *(const u64*)&kv_s[j * 64 + 2 * tx];       // LDS.64
                u64 vp1 = *(const u64*)&kv_s[j * 64 + 2 * tx + 32];
#pragma unroll
                for (int ii = 0; ii < 4; ii++) {
                    u64 pb = pack2(pa[ii][u], pa[ii][u]);
                    oacc[ii][0] = ffma2(pb, vp0, oacc[ii][0]);
                    oacc[ii][1] = ffma2(pb, vp1, oacc[ii][1]);
                }
            }
        }
#pragma unroll
        for (int ii = 0; ii < 4; ii++) {
            int i = ty + ii * 16;
            float inv = row_inv[ii];
            size_t base = (((size_t)b * PH + h) * PS + st_k[i]) * (size_t)PD;
#pragma unroll
            for (int g = 0; g < 2; g++) {
                float2 a = unpack2(oacc[ii][g]);
                a.x *= inv; a.y *= inv;
                *(__half2*)&g_o[base + 2 * tx + 32 * g] =
                    __floats2half2_rn(a.x, a.y);          // STG.32, coalesced
            }
        }
    }
}

// ---------------------------------------------------------------------------
// no-op launch: shifts the fixed ncu capture slot (our 4th launch) onto k_attn
// ---------------------------------------------------------------------------
__global__ void k_nop() {}

// ---------------------------------------------------------------------------
// Kernel 4: combine hash rounds: w_h = exp(lse_h - logsumexp_h), out = sum w_h o_h.
// fp16 g_o read as half2 pairs; fp32 accumulate + output.
// ---------------------------------------------------------------------------
__global__ void __launch_bounds__(256) k_combine(float* __restrict__ out)
{
    __shared__ float sw[32 * 8];
    int b  = blockIdx.x >> 7;
    int t0 = (blockIdx.x & 127) * 32;
    int tid = threadIdx.x;
    int tl = tid >> 3, h = tid & 7;
    int t = t0 + tl;

    float l = g_lse[((size_t)b * PH + h) * PS + t];
    float m = l;
#pragma unroll
    for (int o = 4; o; o >>= 1) m = fmaxf(m, __shfl_xor_sync(0xffffffffu, m, o));
    float s = __expf(l - m);
#pragma unroll
    for (int o = 4; o; o >>= 1) s += __shfl_xor_sync(0xffffffffu, s, o);
    sw[tl * 8 + h] = __expf(l - (m + __logf(s)));
    __syncthreads();

    // 32 tokens x 32 d-pairs = 1024 pairs, 4 per thread
#pragma unroll
    for (int r = 0; r < 4; r++) {
        int idx = tid + r * 256;
        int tl2 = idx >> 5, dp = idx & 31;
        int t2 = t0 + tl2;
        float ax = 0.f, ay = 0.f;
#pragma unroll
        for (int hh = 0; hh < 8; hh++) {
            __half2 hv = *(const __half2*)
                &g_o[(((size_t)b * PH + hh) * PS + t2) * (size_t)PD + 2 * dp];
            float2 f = __half22float2(hv);
            float w = sw[tl2 * 8 + hh];
            ax += f.x * w; ay += f.y * w;
        }
        float2 res = make_float2(ax, ay);
        *(float2*)&out[((size_t)b * PS + t2) * (size_t)PD + 2 * dp] = res;
    }
}

// ---------------------------------------------------------------------------
extern "C" void kernel_launch(void* const* d_in, const int* in_sizes, int n_in,
                              void* d_out, int out_size)
{
    (void)n_in; (void)in_sizes;
    const float* qk  = (const float*)d_in[0];
    const float* v   = (const float*)d_in[1];
    const float* rot = (const float*)d_in[2];
    float* out = (float*)d_out;

    const int n_main = PB * PS * PD;            // 4194304
    const int n_buck = PB * PH * PS;            // 524288
    int write_buckets = (out_size >= n_main + n_buck) ? 1 : 0;

    cudaFuncSetAttribute(k_attn, cudaFuncAttributeMaxDynamicSharedMemorySize,
                         SMEM3_BYTES);

    k_hash<<<PB * (PS / 256), 256>>>(qk, rot, out + n_main, write_buckets);
    k_sort<<<PB * PH, 128>>>();
    k_nop<<<1, 32>>>();   // capture slot #4 (2 harness launches + these) = k_attn
    k_attn<<<PB * PCHUNKS, 256, SMEM3_BYTES>>>(qk, v);
    k_combine<<<PB * (PS / 32), 256>>>(out);
}